// round 1
// baseline (speedup 1.0000x reference)
#include <cuda_runtime.h>
#include <cstdint>
#include <cstddef>

// Problem constants
#define T_  4
#define B_  1024
#define S_  64          // WH*WW
#define C_  256
#define NH_ 8
#define Y_ELEMS (67108864LL)   // T*B*S*C = 4*1024*64*256

// ---------------- device scratch (no allocations allowed) ----------------
__device__ float2   g_Wqk[C_ * C_];          // [c][j] -> (Wq[j][c], Wk[j][c])   512 KB
__device__ float    g_WpT[C_ * C_];          // [c][j]                           256 KB
__device__ uint32_t g_kbits[T_ * B_ * S_ * 8];   // k spikes bitpacked, 8 MB
__device__ uint8_t  g_att[T_ * B_ * NH_ * S_];   // att spikes as bytes, 2 MB

// ---------------- K0: coalesced weight transpose ----------------
__global__ void prep_weights(const float* __restrict__ Wq,
                             const float* __restrict__ Wk,
                             const float* __restrict__ Wp) {
    __shared__ float tq[32][33], tk[32][33], tp[32][33];
    int tx = threadIdx.x, ty = threadIdx.y;
    int j0 = blockIdx.y * 32, c0 = blockIdx.x * 32;
    tq[ty][tx] = Wq[(j0 + ty) * C_ + c0 + tx];
    tk[ty][tx] = Wk[(j0 + ty) * C_ + c0 + tx];
    tp[ty][tx] = Wp[(j0 + ty) * C_ + c0 + tx];
    __syncthreads();
    int c = c0 + ty, j = j0 + tx;
    g_Wqk[c * C_ + j] = make_float2(tq[tx][ty], tk[tx][ty]);
    g_WpT[c * C_ + j] = tp[tx][ty];
}

// ---------------- K_A: lif(x) -> sparse Q/K matvec -> lif -> k bits + att ----------------
// One CTA per (b, s). 256 threads: thread j = output channel. Warp w = head w.
__global__ void __launch_bounds__(256) kernelA(const float* __restrict__ x,
                                               const float* __restrict__ pos) {
    const int s = blockIdx.x;
    const int b = blockIdx.y;
    const int j = threadIdx.x;
    const int warp = j >> 5, lane = j & 31;

    __shared__ uint32_t xs_mask[T_][8];

    // Phase 1: LIF over time on raw input; build per-t channel bitmasks.
    {
        float v = 0.0f;
        const float* xp = x + (size_t)b * 16384 + (size_t)s * 256 + j;
#pragma unroll
        for (int t = 0; t < T_; t++) {
            float xv = __ldg(xp + (size_t)t * 16777216);
            v += (xv - v) * 0.5f;                 // v + (x - v)/tau, tau=2
            bool sp = (v - 1.0f) >= 0.0f;         // spike(v - v_th)
            uint32_t m = __ballot_sync(0xffffffffu, sp);
            if (sp) v = 0.0f;                     // hard reset
            if (lane == 0) xs_mask[t][warp] = m;
        }
    }
    __syncthreads();

    // Phase 2: sparse accumulation of Wq/Wk columns over active channels,
    // LIF per output channel, k bitpack, per-head q popcount -> att LIF.
    float vq = 0.0f, vk = 0.0f, va = 0.0f;
    const float* posp = pos + (size_t)s * 256 + j;

#pragma unroll
    for (int t = 0; t < T_; t++) {
        float aq = 0.0f;
        float ak = __ldg(posp + t * 16384);
#pragma unroll
        for (int w = 0; w < 8; w++) {
            uint32_t m = xs_mask[t][w];
            while (m) {
                int c = (w << 5) + __ffs(m) - 1;
                m &= m - 1;
                float2 wv = g_Wqk[c * C_ + j];
                aq += wv.x;
                ak += wv.y;
            }
        }
        // q LIF
        vq += (aq - vq) * 0.5f;
        bool sq = (vq - 1.0f) >= 0.0f;
        if (sq) vq = 0.0f;
        // k LIF
        vk += (ak - vk) * 0.5f;
        bool sk = (vk - 1.0f) >= 0.0f;
        if (sk) vk = 0.0f;

        uint32_t km = __ballot_sync(0xffffffffu, sk);
        if (lane == 0)
            g_kbits[(((size_t)t * B_ + b) * S_ + s) * 8 + warp] = km;

        // per-head q sum (warp == head), exact integer
        int cnt = __popc(__ballot_sync(0xffffffffu, sq));
        va += ((float)cnt - va) * 0.5f;
        bool sa = (va - 1.0f) >= 0.0f;
        if (sa) va = 0.0f;
        if (lane == 0)
            g_att[(((size_t)t * B_ + b) * NH_ + warp) * S_ + s] = sa ? 1u : 0u;
    }
}

// ---------------- K_B: gather x2 bits, sparse Wp matvec + bias, write y ----------------
// One CTA per output (b, s). Thread j = (h,d): h=j>>5, d=j&31.
__global__ void __launch_bounds__(256) kernelB(const float* __restrict__ bp,
                                               float* __restrict__ out) {
    const int s = blockIdx.x;
    const int b = blockIdx.y;
    const int j = threadIdx.x;
    const int h = j >> 5, d = j & 31;
    const int wh = s >> 3, ww = s & 7;

    const int t_k = b >> 8;
    const int b_k = (b & 255) * 4 + (h >> 1);

    __shared__ uint32_t x2m[T_][8];

#pragma unroll
    for (int t = 0; t < T_; t++) {
        int s_k = ((h & 1) << 5) + t * 8 + wh;
        uint32_t kw = g_kbits[(((size_t)t_k * B_ + b_k) * S_ + s_k) * 8 + ww];
        uint8_t ab = g_att[(((size_t)t_k * B_ + b_k) * NH_ + ((h & 1) * 4 + t)) * S_ + s];
        bool x2 = (((kw >> d) & 1u) != 0u) && (ab != 0u);
        uint32_t m = __ballot_sync(0xffffffffu, x2);
        if (d == 0) x2m[t][h] = m;
    }
    __syncthreads();

    const float bias = __ldg(bp + j);
#pragma unroll
    for (int t = 0; t < T_; t++) {
        float acc = bias;
#pragma unroll
        for (int w = 0; w < 8; w++) {
            uint32_t m = x2m[t][w];
            while (m) {
                int c = (w << 5) + __ffs(m) - 1;
                m &= m - 1;
                acc += g_WpT[c * C_ + j];
            }
        }
        size_t off = (((size_t)t * B_ + b) * S_ + s) * 256 + j;
        out[off] = acc;
    }
}

// ---------------- K_C: attn_out is provably identically zero ----------------
// x2 in {0,1}; LIF v <- (v+x)/2 stays strictly below 1 (exact dyadic fp32),
// so spike(v-1) never fires. Reference computes the same exact arithmetic.
__global__ void zfill(float4* __restrict__ p, size_t n4) {
    size_t i = (size_t)blockIdx.x * blockDim.x + threadIdx.x;
    size_t stride = (size_t)gridDim.x * blockDim.x;
    float4 z = make_float4(0.f, 0.f, 0.f, 0.f);
    for (; i < n4; i += stride) p[i] = z;
}

__global__ void zfill_tail(float* __restrict__ p, size_t n) {
    size_t i = (size_t)blockIdx.x * blockDim.x + threadIdx.x;
    if (i < n) p[i] = 0.f;
}

extern "C" void kernel_launch(void* const* d_in, const int* in_sizes, int n_in,
                              void* d_out, int out_size) {
    const float* x   = (const float*)d_in[0];
    const float* Wq  = (const float*)d_in[1];
    const float* Wk  = (const float*)d_in[2];
    const float* Wp  = (const float*)d_in[3];
    const float* bp  = (const float*)d_in[4];
    const float* pos = (const float*)d_in[5];
    float* out = (float*)d_out;

    prep_weights<<<dim3(8, 8), dim3(32, 32)>>>(Wq, Wk, Wp);
    kernelA<<<dim3(64, 1024), 256>>>(x, pos);
    kernelB<<<dim3(64, 1024), 256>>>(bp, out);

    long long extra = (long long)out_size - Y_ELEMS;
    if (extra > 0) {
        size_t n = (size_t)extra;
        size_t n4 = n / 4;
        if (n4 > 0)
            zfill<<<2048, 256>>>((float4*)(out + Y_ELEMS), n4);
        size_t tail = n - n4 * 4;
        if (tail > 0)
            zfill_tail<<<1, 256>>>(out + Y_ELEMS + n4 * 4, tail);
    }
}